// round 8
// baseline (speedup 1.0000x reference)
#include <cuda_runtime.h>
#include <math.h>

#define BATCH   32
#define SEQ     12
#define FEAT    128
#define KHEADS  8
#define HDIM    64
#define CDIM    64
#define NNODE   512
#define WF_COLS (NNODE * CDIM)    // 32768 floats per Wf row
#define NCONS   (2 * CDIM)        // 128 consumer blocks (2 per Wf row)

// Inter-block handshake state (zero-init; reset before kernel exit)
__device__ float    g_who[BATCH * CDIM];
__device__ float    g_half[CDIM * CDIM];   // h=1 partial row sums
__device__ unsigned g_hflag[CDIM];         // per-row half-ready flags
__device__ unsigned g_ready;               // producers completed (0..32)
__device__ unsigned g_done;                // h=0 consumers completed (0..64)

// ---------------------------------------------------------------------------
// One fused kernel, 160 blocks x 512 threads:
//   blocks 0..31    : producers — who[b] = elu(x_last @ W_heads) @ W_out
//   blocks 32..159  : consumers — pair (cp, h) streams half a Wf row
//                     (64 KB, front-batched float4) ; h=0 combines halves,
//                     waits for who, emits out[:, cp] fused.
// Attention blocks are exactly identity (all N nodes identical -> softmax
// uniform -> att @ Wh == Wh); a1*/a2* inputs are mathematically dead.
// ---------------------------------------------------------------------------
__global__ __launch_bounds__(512, 1) void fused_kernel(
    const float* __restrict__ x,         // (32,12,128)
    const float* __restrict__ W_heads,   // (8,128,64)
    const float* __restrict__ W_out,     // (512,64)
    const float* __restrict__ Wf,        // (64,32768)
    const float* __restrict__ bf,        // (64)
    float* __restrict__ out)             // (32,64)
{
    const int t = threadIdx.x;
    __shared__ float4 red[512];          // 8 KB reduction scratch

    if (blockIdx.x < BATCH) {
        // =================== producer: who[b] ===========================
        const int b = blockIdx.x;
        __shared__ float s_x[FEAT];
        __shared__ float s_h[KHEADS * HDIM];

        if (t < FEAT)
            s_x[t] = x[((size_t)b * SEQ + (SEQ - 1)) * FEAT + t];
        __syncthreads();

        // Wh: 128 (k,h4) float4 outputs; 4 threads split f; loads batched x8
        {
            const int p   = t >> 2;      // k*16 + h4
            const int sub = t & 3;
            const int k   = p >> 4;
            const int h4  = p & 15;
            const int f0  = sub * 32;
            const float4* Wp = reinterpret_cast<const float4*>(W_heads)
                               + (k * FEAT + f0) * 16 + h4;
            float4 acc = make_float4(0.f, 0.f, 0.f, 0.f);
#pragma unroll
            for (int blk = 0; blk < 4; blk++) {
                float4 w[8];
#pragma unroll
                for (int j = 0; j < 8; j++)
                    w[j] = Wp[(blk * 8 + j) * 16];
#pragma unroll
                for (int j = 0; j < 8; j++) {
                    const float xv = s_x[f0 + blk * 8 + j];
                    acc.x += xv * w[j].x; acc.y += xv * w[j].y;
                    acc.z += xv * w[j].z; acc.w += xv * w[j].w;
                }
            }
            red[t] = acc;
        }
        __syncthreads();
        if (t < 128) {
            float4 a = red[4*t], b1 = red[4*t+1], c1 = red[4*t+2], d = red[4*t+3];
            float v0 = a.x + b1.x + c1.x + d.x;
            float v1 = a.y + b1.y + c1.y + d.y;
            float v2 = a.z + b1.z + c1.z + d.z;
            float v3 = a.w + b1.w + c1.w + d.w;
            s_h[4*t+0] = (v0 > 0.f) ? v0 : expm1f(v0);   // elu
            s_h[4*t+1] = (v1 > 0.f) ? v1 : expm1f(v1);
            s_h[4*t+2] = (v2 > 0.f) ? v2 : expm1f(v2);
            s_h[4*t+3] = (v3 > 0.f) ? v3 : expm1f(v3);
        }
        __syncthreads();

        // Wh_o: 16 c-float4 outputs; 32 groups split f; loads batched x8
        {
            const int c4  = t & 15;
            const int grp = t >> 4;
            const float4* Wo = reinterpret_cast<const float4*>(W_out)
                               + grp * 16 * 16 + c4;
            float4 acc = make_float4(0.f, 0.f, 0.f, 0.f);
#pragma unroll
            for (int blk = 0; blk < 2; blk++) {
                float4 w[8];
#pragma unroll
                for (int j = 0; j < 8; j++)
                    w[j] = Wo[(blk * 8 + j) * 16];
#pragma unroll
                for (int j = 0; j < 8; j++) {
                    const float hv = s_h[grp * 16 + blk * 8 + j];
                    acc.x += hv * w[j].x; acc.y += hv * w[j].y;
                    acc.z += hv * w[j].z; acc.w += hv * w[j].w;
                }
            }
            red[t] = acc;
        }
        __syncthreads();
#pragma unroll
        for (int off = 256; off >= 16; off >>= 1) {
            if (t < off) {
                float4 a = red[t], bv = red[t + off];
                a.x += bv.x; a.y += bv.y; a.z += bv.z; a.w += bv.w;
                red[t] = a;
            }
            __syncthreads();
        }
        if (t < 16)
            reinterpret_cast<float4*>(g_who)[b * 16 + t] = red[t];
        __syncthreads();
        if (t == 0) {
            __threadfence();                 // release g_who (cumulative)
            atomicAdd(&g_ready, 1u);
        }
    } else {
        // ============== consumer: half-row (cp, h) of Wf ================
        const int idx = blockIdx.x - BATCH;  // 0..127
        const int cp  = idx >> 1;            // 0..63
        const int h   = idx & 1;             // which half of the 512 n's

        // stream + reduce 64 KB: thread = (c4, grp), 8 front-batched float4
        {
            const float4* row = reinterpret_cast<const float4*>(
                Wf + (size_t)cp * WF_COLS);
            const int c4  = t & 15;
            const int grp = t >> 4;          // 0..31, each 8 n's
            const int n0  = h * 256 + grp * 8;
            float4 v[8];
#pragma unroll
            for (int j = 0; j < 8; j++)
                v[j] = row[(n0 + j) * 16 + c4];
            float4 acc = make_float4(0.f, 0.f, 0.f, 0.f);
#pragma unroll
            for (int j = 0; j < 8; j++) {
                acc.x += v[j].x; acc.y += v[j].y;
                acc.z += v[j].z; acc.w += v[j].w;
            }
            red[t] = acc;
        }
        __syncthreads();
#pragma unroll
        for (int off = 256; off >= 16; off >>= 1) {
            if (t < off) {
                float4 a = red[t], bv = red[t + off];
                a.x += bv.x; a.y += bv.y; a.z += bv.z; a.w += bv.w;
                red[t] = a;
            }
            __syncthreads();
        }

        if (h == 1) {
            // publish partial + release flag, then exit (never spins)
            if (t < 16)
                reinterpret_cast<float4*>(g_half)[cp * 16 + t] = red[t];
            __syncthreads();
            if (t == 0) {
                __threadfence();
                atomicExch(&g_hflag[cp], 1u);
            }
            return;
        }

        // ---------------- h == 0: combine + fused output ----------------
        __shared__ float s_wf[CDIM];
        __shared__ float s_who[BATCH * 65]; // padded: conflict-free dot

        if (t == 0) {
            volatile unsigned* fp = &g_hflag[cp];
            volatile unsigned* rp = &g_ready;
            while (*fp == 0u || *rp < BATCH) { __nanosleep(32); }
            __threadfence();                 // acquire g_half + g_who
            *fp = 0u;                        // reset flag for next replay
        }
        __syncthreads();

        if (t < 16) {
            const float4 a = red[t];
            const float4 p = reinterpret_cast<const float4*>(g_half)[cp * 16 + t];
            s_wf[4*t+0] = a.x + p.x; s_wf[4*t+1] = a.y + p.y;
            s_wf[4*t+2] = a.z + p.z; s_wf[4*t+3] = a.w + p.w;
        }
        // stage who into padded smem (coalesced)
#pragma unroll
        for (int i = t; i < BATCH * CDIM; i += 512)
            s_who[(i >> 6) * 65 + (i & 63)] = g_who[i];
        __syncthreads();

        if (t < BATCH) {
            float acc = bf[cp];
#pragma unroll
            for (int c = 0; c < CDIM; c++)
                acc += s_who[t * 65 + c] * s_wf[c];
            out[(size_t)t * CDIM + cp] = acc;
        }
        __syncthreads();

        // last h==0 consumer resets shared handshake state
        if (t == 0) {
            unsigned old = atomicAdd(&g_done, 1u);
            if (old == CDIM - 1) {
                g_ready = 0u;
                __threadfence();
                g_done = 0u;
            }
        }
    }
}

// ---------------------------------------------------------------------------
// Inputs (metadata order): 0:x 1:W_heads 2:a1_heads 3:a2_heads 4:W_out
// 5:a1_out 6:a2_out 7:Wf 8:bf.  Output float32 (32,64).
// ---------------------------------------------------------------------------
extern "C" void kernel_launch(void* const* d_in, const int* in_sizes, int n_in,
                              void* d_out, int out_size) {
    const float* x       = (const float*)d_in[0];
    const float* W_heads = (const float*)d_in[1];
    const float* W_out   = (const float*)d_in[4];
    const float* Wf      = (const float*)d_in[7];
    const float* bf      = (const float*)d_in[8];
    float* out = (float*)d_out;

    fused_kernel<<<BATCH + NCONS, 512>>>(x, W_heads, W_out, Wf, bf, out);
}

// round 10
// speedup vs baseline: 1.4310x; 1.4310x over previous
#include <cuda_runtime.h>
#include <math.h>

#define BATCH   32
#define SEQ     12
#define FEAT    128
#define KHEADS  8
#define HDIM    64
#define CDIM    64
#define NNODE   512
#define WF_COLS (NNODE * CDIM)    // 32768 floats per Wf row

// Inter-block handshake state (zero-init; reset before kernel exit)
__device__ float    g_who[BATCH * CDIM];
__device__ unsigned g_ready;     // producers completed (0..32)
__device__ unsigned g_done;      // consumers completed (0..64)

// ---------------------------------------------------------------------------
// One fused kernel, 96 blocks x 512 threads — SINGLE WAVE (96 < 148 SMs):
//   blocks 0..31  : producers — who[b] = elu(x_last @ W_heads) @ W_out
//   blocks 32..95 : consumers — stream full 128 KB Wf row with a 16-deep
//                   front-batched float4 load (MLP=16/thread), reduce,
//                   wait for who, emit out[:, cp] fused.
// Attention blocks are exactly identity (all N nodes identical -> softmax
// uniform -> att @ Wh == Wh); a1*/a2* inputs are mathematically dead.
// ---------------------------------------------------------------------------
__global__ __launch_bounds__(512, 1) void fused_kernel(
    const float* __restrict__ x,         // (32,12,128)
    const float* __restrict__ W_heads,   // (8,128,64)
    const float* __restrict__ W_out,     // (512,64)
    const float* __restrict__ Wf,        // (64,32768)
    const float* __restrict__ bf,        // (64)
    float* __restrict__ out)             // (32,64)
{
    const int t = threadIdx.x;
    __shared__ float4 red[512];          // 8 KB reduction scratch

    if (blockIdx.x < BATCH) {
        // =================== producer: who[b] ===========================
        const int b = blockIdx.x;
        __shared__ float s_x[FEAT];
        __shared__ float s_h[KHEADS * HDIM];

        if (t < FEAT)
            s_x[t] = x[((size_t)b * SEQ + (SEQ - 1)) * FEAT + t];
        __syncthreads();

        // Wh: 128 (k,h4) float4 outputs; 4 threads split f; loads batched x8
        {
            const int p   = t >> 2;      // k*16 + h4
            const int sub = t & 3;
            const int k   = p >> 4;
            const int h4  = p & 15;
            const int f0  = sub * 32;
            const float4* Wp = reinterpret_cast<const float4*>(W_heads)
                               + (k * FEAT + f0) * 16 + h4;
            float4 acc = make_float4(0.f, 0.f, 0.f, 0.f);
#pragma unroll
            for (int blk = 0; blk < 4; blk++) {
                float4 w[8];
#pragma unroll
                for (int j = 0; j < 8; j++)
                    w[j] = Wp[(blk * 8 + j) * 16];
#pragma unroll
                for (int j = 0; j < 8; j++) {
                    const float xv = s_x[f0 + blk * 8 + j];
                    acc.x += xv * w[j].x; acc.y += xv * w[j].y;
                    acc.z += xv * w[j].z; acc.w += xv * w[j].w;
                }
            }
            red[t] = acc;
        }
        __syncthreads();
        if (t < 128) {
            float4 a = red[4*t], b1 = red[4*t+1], c1 = red[4*t+2], d = red[4*t+3];
            float v0 = a.x + b1.x + c1.x + d.x;
            float v1 = a.y + b1.y + c1.y + d.y;
            float v2 = a.z + b1.z + c1.z + d.z;
            float v3 = a.w + b1.w + c1.w + d.w;
            s_h[4*t+0] = (v0 > 0.f) ? v0 : expm1f(v0);   // elu
            s_h[4*t+1] = (v1 > 0.f) ? v1 : expm1f(v1);
            s_h[4*t+2] = (v2 > 0.f) ? v2 : expm1f(v2);
            s_h[4*t+3] = (v3 > 0.f) ? v3 : expm1f(v3);
        }
        __syncthreads();

        // Wh_o: 16 c-float4 outputs; 32 groups split f; loads batched x8
        {
            const int c4  = t & 15;
            const int grp = t >> 4;
            const float4* Wo = reinterpret_cast<const float4*>(W_out)
                               + grp * 16 * 16 + c4;
            float4 acc = make_float4(0.f, 0.f, 0.f, 0.f);
#pragma unroll
            for (int blk = 0; blk < 2; blk++) {
                float4 w[8];
#pragma unroll
                for (int j = 0; j < 8; j++)
                    w[j] = Wo[(blk * 8 + j) * 16];
#pragma unroll
                for (int j = 0; j < 8; j++) {
                    const float hv = s_h[grp * 16 + blk * 8 + j];
                    acc.x += hv * w[j].x; acc.y += hv * w[j].y;
                    acc.z += hv * w[j].z; acc.w += hv * w[j].w;
                }
            }
            red[t] = acc;
        }
        __syncthreads();
#pragma unroll
        for (int off = 256; off >= 16; off >>= 1) {
            if (t < off) {
                float4 a = red[t], bv = red[t + off];
                a.x += bv.x; a.y += bv.y; a.z += bv.z; a.w += bv.w;
                red[t] = a;
            }
            __syncthreads();
        }
        if (t < 16)
            reinterpret_cast<float4*>(g_who)[b * 16 + t] = red[t];
        __syncthreads();
        if (t == 0) {
            __threadfence();                 // release g_who (cumulative)
            atomicAdd(&g_ready, 1u);
        }
    } else {
        // ============== consumer: full Wf row cp =========================
        const int cp = blockIdx.x - BATCH;   // 0..63
        __shared__ float s_wf[CDIM];
        __shared__ float s_who[BATCH * 65];  // padded: conflict-free dot

        // stream + reduce 128 KB: 16-deep front-batched float4 per thread
        {
            const float4* row = reinterpret_cast<const float4*>(
                Wf + (size_t)cp * WF_COLS);
            const int c4  = t & 15;
            const int grp = t >> 4;          // 0..31, each covers 16 n's
            float4 v[16];
#pragma unroll
            for (int j = 0; j < 16; j++)     // all 16 LDG.128 issued first
                v[j] = row[(grp * 16 + j) * 16 + c4];
#pragma unroll
            for (int s = 8; s >= 1; s >>= 1) // pairwise: short dep chains
#pragma unroll
                for (int j = 0; j < s; j++) {
                    v[j].x += v[j + s].x; v[j].y += v[j + s].y;
                    v[j].z += v[j + s].z; v[j].w += v[j + s].w;
                }
            red[t] = v[0];
        }
        __syncthreads();
#pragma unroll
        for (int off = 256; off >= 16; off >>= 1) {
            if (t < off) {
                float4 a = red[t], bv = red[t + off];
                a.x += bv.x; a.y += bv.y; a.z += bv.z; a.w += bv.w;
                red[t] = a;
            }
            __syncthreads();
        }
        if (t < 16) {
            const float4 a = red[t];
            s_wf[4*t+0] = a.x; s_wf[4*t+1] = a.y;
            s_wf[4*t+2] = a.z; s_wf[4*t+3] = a.w;
        }

        // wait for producers (leader spins, then block-wide acquire)
        if (t == 0) {
            volatile unsigned* rp = &g_ready;
            while (*rp < BATCH) { __nanosleep(32); }
            __threadfence();                 // acquire g_who (cumulative)
        }
        __syncthreads();

        // stage who into padded smem (coalesced)
#pragma unroll
        for (int i = t; i < BATCH * CDIM; i += 512)
            s_who[(i >> 6) * 65 + (i & 63)] = g_who[i];
        __syncthreads();

        // fused final GEMV for this channel
        if (t < BATCH) {
            float acc = bf[cp];
#pragma unroll
            for (int c = 0; c < CDIM; c++)
                acc += s_who[t * 65 + c] * s_wf[c];
            out[(size_t)t * CDIM + cp] = acc;
        }
        __syncthreads();

        // last consumer resets handshake state for the next replay
        if (t == 0) {
            unsigned old = atomicAdd(&g_done, 1u);
            if (old == CDIM - 1) {
                g_ready = 0u;
                __threadfence();
                g_done = 0u;
            }
        }
    }
}

// ---------------------------------------------------------------------------
// Inputs (metadata order): 0:x 1:W_heads 2:a1_heads 3:a2_heads 4:W_out
// 5:a1_out 6:a2_out 7:Wf 8:bf.  Output float32 (32,64).
// ---------------------------------------------------------------------------
extern "C" void kernel_launch(void* const* d_in, const int* in_sizes, int n_in,
                              void* d_out, int out_size) {
    const float* x       = (const float*)d_in[0];
    const float* W_heads = (const float*)d_in[1];
    const float* W_out   = (const float*)d_in[4];
    const float* Wf      = (const float*)d_in[7];
    const float* bf      = (const float*)d_in[8];
    float* out = (float*)d_out;

    fused_kernel<<<BATCH + CDIM, 512>>>(x, W_heads, W_out, Wf, bf, out);
}

// round 12
// speedup vs baseline: 1.4341x; 1.0022x over previous
#include <cuda_runtime.h>
#include <math.h>

#define BATCH   32
#define SEQ     12
#define FEAT    128
#define KHEADS  8
#define HDIM    64
#define CDIM    64
#define NNODE   512
#define WF_COLS (NNODE * CDIM)    // 32768 floats per Wf row
#define NPROD   16                // producer blocks (2 batches each)
#define NCONS   128               // consumer blocks (2 per Wf row)
// total grid = 144 <= 148 SMs -> single wave (spin handshake is safe)

// Inter-block handshake state (zero-init; reset before kernel exit)
__device__ float    g_who[BATCH * CDIM];
__device__ float    g_half[CDIM * CDIM];   // h=1 partial row sums (64/row)
__device__ unsigned g_hflag[CDIM];         // per-row half-ready flags
__device__ unsigned g_ready;               // producers completed (0..16)
__device__ unsigned g_done;                // h=0 consumers completed (0..64)

// ---------------------------------------------------------------------------
// One fused kernel, 144 blocks x 512 threads — SINGLE WAVE:
//   blocks 0..15    : producers — two 256-thread halves, each computes
//                     who[b] = elu(x_last @ W_heads) @ W_out for one batch
//   blocks 16..143  : consumers — pair (cp, h) streams HALF a Wf row
//                     (64 KB, 8-deep front-batched float4); h=1 publishes
//                     its partial; h=0 combines, waits for who, emits
//                     out[:, cp] fused.
// Attention blocks are exactly identity (all N nodes identical -> softmax
// uniform -> att @ Wh == Wh); a1*/a2* inputs are mathematically dead.
// ---------------------------------------------------------------------------
__global__ __launch_bounds__(512, 1) void fused_kernel(
    const float* __restrict__ x,         // (32,12,128)
    const float* __restrict__ W_heads,   // (8,128,64)
    const float* __restrict__ W_out,     // (512,64)
    const float* __restrict__ Wf,        // (64,32768)
    const float* __restrict__ bf,        // (64)
    float* __restrict__ out)             // (32,64)
{
    const int t = threadIdx.x;
    __shared__ float4 red[512];          // 8 KB reduction scratch

    if (blockIdx.x < NPROD) {
        // ============ producer: batches 2*bid and 2*bid+1 ===============
        const int half = t >> 8;         // which batch half-block
        const int tt   = t & 255;
        const int b    = blockIdx.x * 2 + half;
        __shared__ float s_x[2][FEAT];
        __shared__ float s_h[2][KHEADS * HDIM];

        if (t < 256) {
            const int hb = t >> 7, f = t & 127;
            s_x[hb][f] = x[((size_t)(blockIdx.x * 2 + hb) * SEQ + (SEQ - 1))
                           * FEAT + f];
        }
        __syncthreads();

        // Wh: 128 (k,h4) float4 outputs per batch; 2 threads split f (64 ea)
        {
            const int p   = tt >> 1;     // k*16 + h4
            const int sub = tt & 1;
            const int k   = p >> 4;
            const int h4  = p & 15;
            const int f0  = sub * 64;
            const float4* Wp = reinterpret_cast<const float4*>(W_heads)
                               + (k * FEAT + f0) * 16 + h4;
            float4 acc = make_float4(0.f, 0.f, 0.f, 0.f);
#pragma unroll
            for (int blk = 0; blk < 8; blk++) {
                float4 w[8];
#pragma unroll
                for (int j = 0; j < 8; j++)
                    w[j] = Wp[(blk * 8 + j) * 16];
#pragma unroll
                for (int j = 0; j < 8; j++) {
                    const float xv = s_x[half][f0 + blk * 8 + j];
                    acc.x += xv * w[j].x; acc.y += xv * w[j].y;
                    acc.z += xv * w[j].z; acc.w += xv * w[j].w;
                }
            }
            red[t] = acc;
        }
        __syncthreads();
        if (tt < 128) {
            const int base = half * 256;
            float4 a = red[base + 2 * tt], b1 = red[base + 2 * tt + 1];
            float v0 = a.x + b1.x, v1 = a.y + b1.y;
            float v2 = a.z + b1.z, v3 = a.w + b1.w;
            s_h[half][4*tt+0] = (v0 > 0.f) ? v0 : expm1f(v0);   // elu
            s_h[half][4*tt+1] = (v1 > 0.f) ? v1 : expm1f(v1);
            s_h[half][4*tt+2] = (v2 > 0.f) ? v2 : expm1f(v2);
            s_h[half][4*tt+3] = (v3 > 0.f) ? v3 : expm1f(v3);
        }
        __syncthreads();

        // Wh_o: 16 c-float4 outputs; 16 groups split the 512 f (32 each)
        {
            const int c4  = tt & 15;
            const int grp = tt >> 4;     // 0..15
            const float4* Wo = reinterpret_cast<const float4*>(W_out)
                               + grp * 32 * 16 + c4;
            float4 acc = make_float4(0.f, 0.f, 0.f, 0.f);
#pragma unroll
            for (int blk = 0; blk < 4; blk++) {
                float4 w[8];
#pragma unroll
                for (int j = 0; j < 8; j++)
                    w[j] = Wo[(blk * 8 + j) * 16];
#pragma unroll
                for (int j = 0; j < 8; j++) {
                    const float hv = s_h[half][grp * 32 + blk * 8 + j];
                    acc.x += hv * w[j].x; acc.y += hv * w[j].y;
                    acc.z += hv * w[j].z; acc.w += hv * w[j].w;
                }
            }
            red[t] = acc;
        }
        __syncthreads();
#pragma unroll
        for (int off = 128; off >= 16; off >>= 1) {
            if (tt < off) {
                const int base = half * 256;
                float4 a = red[base + tt], bv = red[base + tt + off];
                a.x += bv.x; a.y += bv.y; a.z += bv.z; a.w += bv.w;
                red[base + tt] = a;
            }
            __syncthreads();
        }
        if (tt < 16)
            reinterpret_cast<float4*>(g_who)[b * 16 + tt] = red[half * 256 + tt];
        __syncthreads();
        if (t == 0) {
            __threadfence();                 // release g_who (cumulative)
            atomicAdd(&g_ready, 1u);
        }
    } else {
        // ============== consumer: half-row (cp, hh) of Wf ===============
        const int idx = blockIdx.x - NPROD;  // 0..127
        const int cp  = idx >> 1;            // 0..63
        const int hh  = idx & 1;             // which 256 n's

        // stream + reduce 64 KB: 8-deep front-batched float4 per thread
        {
            const float4* row = reinterpret_cast<const float4*>(
                Wf + (size_t)cp * WF_COLS);
            const int c4  = t & 15;
            const int grp = t >> 4;          // 0..31, each 8 n's
            const int n0  = hh * 256 + grp * 8;
            float4 v[8];
#pragma unroll
            for (int j = 0; j < 8; j++)
                v[j] = row[(n0 + j) * 16 + c4];
#pragma unroll
            for (int s = 4; s >= 1; s >>= 1)
#pragma unroll
                for (int j = 0; j < s; j++) {
                    v[j].x += v[j + s].x; v[j].y += v[j + s].y;
                    v[j].z += v[j + s].z; v[j].w += v[j + s].w;
                }
            red[t] = v[0];
        }
        __syncthreads();
#pragma unroll
        for (int off = 256; off >= 16; off >>= 1) {
            if (t < off) {
                float4 a = red[t], bv = red[t + off];
                a.x += bv.x; a.y += bv.y; a.z += bv.z; a.w += bv.w;
                red[t] = a;
            }
            __syncthreads();
        }

        if (hh == 1) {
            // publish partial + release flag, then exit (never spins)
            if (t < 16)
                reinterpret_cast<float4*>(g_half)[cp * 16 + t] = red[t];
            __syncthreads();
            if (t == 0) {
                __threadfence();
                atomicExch(&g_hflag[cp], 1u);
            }
            return;
        }

        // ---------------- hh == 0: combine + fused output ---------------
        __shared__ float s_wf[CDIM];
        __shared__ float s_who[BATCH * 65]; // padded: conflict-free dot

        if (t == 0) {
            volatile unsigned* fp = &g_hflag[cp];
            volatile unsigned* rp = &g_ready;
            while (*fp == 0u || *rp < NPROD) { __nanosleep(32); }
            __threadfence();                 // acquire g_half + g_who
            *fp = 0u;                        // reset for next replay
        }
        __syncthreads();

        if (t < 16) {
            const float4 a = red[t];
            const float4 p = reinterpret_cast<const float4*>(g_half)[cp * 16 + t];
            s_wf[4*t+0] = a.x + p.x; s_wf[4*t+1] = a.y + p.y;
            s_wf[4*t+2] = a.z + p.z; s_wf[4*t+3] = a.w + p.w;
        }
        // stage who into padded smem (coalesced)
#pragma unroll
        for (int i = t; i < BATCH * CDIM; i += 512)
            s_who[(i >> 6) * 65 + (i & 63)] = g_who[i];
        __syncthreads();

        // fused final GEMV for this channel
        if (t < BATCH) {
            float acc = bf[cp];
#pragma unroll
            for (int c = 0; c < CDIM; c++)
                acc += s_who[t * 65 + c] * s_wf[c];
            out[(size_t)t * CDIM + cp] = acc;
        }
        __syncthreads();

        // last hh==0 consumer resets shared handshake state
        if (t == 0) {
            unsigned old = atomicAdd(&g_done, 1u);
            if (old == CDIM - 1) {
                g_ready = 0u;
                __threadfence();
                g_done = 0u;
            }
        }
    }
}

// ---------------------------------------------------------------------------
// Inputs (metadata order): 0:x 1:W_heads 2:a1_heads 3:a2_heads 4:W_out
// 5:a1_out 6:a2_out 7:Wf 8:bf.  Output float32 (32,64).
// ---------------------------------------------------------------------------
extern "C" void kernel_launch(void* const* d_in, const int* in_sizes, int n_in,
                              void* d_out, int out_size) {
    const float* x       = (const float*)d_in[0];
    const float* W_heads = (const float*)d_in[1];
    const float* W_out   = (const float*)d_in[4];
    const float* Wf      = (const float*)d_in[7];
    const float* bf      = (const float*)d_in[8];
    float* out = (float*)d_out;

    fused_kernel<<<NPROD + NCONS, 512>>>(x, W_heads, W_out, Wf, bf, out);
}